// round 14
// baseline (speedup 1.0000x reference)
#include <cuda_runtime.h>
#include <stdint.h>

// Shapes (fixed):
//   x:        (B, M, N)  float32          B=32, M=512, N=128
//   location: (B, M, 2)  int64/int32 (y, x), H=W=128
//   out:      (B, N, H, W) float32
#define BB   32
#define MM   512
#define NN   128
#define WPX  128
#define HWPX 16384   // 128*128
#define HW4  4096    // HWPX/4
#define NCH  16      // channels per block
#define TPB  512     // threads per block
#define PPB  2048    // pixels per block (512 threads x 4)

// ---------------------------------------------------------------------------
// CONVERGED KERNEL (best measured: 45.06 us = 5.95 TB/s effective on a
// 95%-write stream; reproduced across three independent benches).
//
// Block = (2048-pixel range, 16-channel chunk, batch); 512 threads at the
// 4-block/SM cap (2048 thr/SM) -> 2048 blocks = 3.46 waves, which the
// R7/R8/R11 grid-scaling experiments showed is required to keep the store
// stream saturated.
//
// Phase A: build 4 KB smem inverse map for this block's 2048-pixel range by
//          scanning batch b's 512 locations (1 per thread, L2-resident).
//          int64-vs-int32 layout detected via __syncthreads_and on odd int32
//          words (all-zero <=> int64; under int32 these are x coords
//          ~U[0,128), P(all 512 zero) ~ 2^-3584).
// Phase B: per q: 4 predicated LDG.128 (one per entity slot), register
//          transpose, 4 streaming STG.128 (warp = 512B contiguous bursts).
//          Only 4 float4s live -> 32 regs, ~83% achieved occupancy.
__global__ void __launch_bounds__(TPB, 4) fused_scatter_kernel(
        const float4* __restrict__ xin,
        const int*    __restrict__ loc32,
        float4*       __restrict__ out) {
    __shared__ short s_inv[PPB];

    const int t  = threadIdx.x;
    const int b  = blockIdx.z;
    const int n0 = blockIdx.y * NCH;
    const int p0 = blockIdx.x * PPB;          // first pixel of this block

    // --- Phase A: smem inverse map ----------------------------------------
    ((int*)s_inv)[2 * t]     = -1;            // 4 shorts = -1 per thread
    ((int*)s_inv)[2 * t + 1] = -1;

    const int* locb32 = loc32 + b * MM * 2;   // int32 view of batch b
    const int* locb64 = loc32 + b * MM * 4;   // int64 view (int32 pairs)

    // layout probe (doubles as the barrier ordering smem init vs scatter):
    int is64 = __syncthreads_and(loc32[2 * t + 1] == 0);

    {
        int e = t;                            // entity m in [0, 512)
        int y, x;
        if (is64) { y = locb64[4 * e]; x = locb64[4 * e + 2]; }
        else      { y = locb32[2 * e]; x = locb32[2 * e + 1]; }
        int rel = y * WPX + x - p0;
        if ((unsigned)rel < PPB) s_inv[rel] = (short)e;
    }
    __syncthreads();

    // --- Phase B: pipelined gather + zero-fill ----------------------------
    short4 iv = ((const short4*)s_inv)[t];
    int m0 = iv.x, m1 = iv.y, m2 = iv.z, m3 = iv.w;
    bool v0 = m0 >= 0, v1 = m1 >= 0, v2 = m2 >= 0, v3 = m3 >= 0;
    int i0 = m0 * (NN / 4), i1 = m1 * (NN / 4);
    int i2 = m2 * (NN / 4), i3 = m3 * (NN / 4);

    // x[b][m][n0 + 0..15] = 4 float4s at row stride NN/4 = 32.
    const float4* xb = xin + b * (MM * NN / 4) + (n0 >> 2);
    float4*       o  = out + (b * NN + n0) * HW4 + (p0 >> 2) + t;
    const float4  z  = make_float4(0.f, 0.f, 0.f, 0.f);

    #pragma unroll
    for (int q = 0; q < 4; q++) {
        float4 a = v0 ? __ldg(xb + i0 + q) : z;
        float4 c = v1 ? __ldg(xb + i1 + q) : z;
        float4 d = v2 ? __ldg(xb + i2 + q) : z;
        float4 f = v3 ? __ldg(xb + i3 + q) : z;

        __stcs(o + (4 * q + 0) * HW4, make_float4(a.x, c.x, d.x, f.x));
        __stcs(o + (4 * q + 1) * HW4, make_float4(a.y, c.y, d.y, f.y));
        __stcs(o + (4 * q + 2) * HW4, make_float4(a.z, c.z, d.z, f.z));
        __stcs(o + (4 * q + 3) * HW4, make_float4(a.w, c.w, d.w, f.w));
    }
}

// ---------------------------------------------------------------------------
extern "C" void kernel_launch(void* const* d_in, const int* in_sizes, int n_in,
                              void* d_out, int out_size) {
    const float* x     = (const float*)d_in[0];
    const int*   loc32 = (const int*)d_in[1];
    float*       out   = (float*)d_out;
    (void)in_sizes; (void)n_in; (void)out_size;

    // One launch: (8 pixel-ranges, 8 channel-chunks, 32 batches) x 512 thr.
    fused_scatter_kernel<<<dim3(HWPX / PPB, NN / NCH, BB), TPB>>>(
        (const float4*)x, loc32, (float4*)out);
}

// round 15
// speedup vs baseline: 1.0007x; 1.0007x over previous
#include <cuda_runtime.h>
#include <stdint.h>

// Shapes (fixed):
//   x:        (B, M, N)  float32          B=32, M=512, N=128
//   location: (B, M, 2)  int64/int32 (y, x), H=W=128
//   out:      (B, N, H, W) float32
#define BB   32
#define MM   512
#define NN   128
#define WPX  128
#define HWPX 16384   // 128*128
#define HW4  4096    // HWPX/4
#define NCH  16      // channels per block
#define TPB  512     // threads per block
#define PPB  2048    // pixels per block (512 threads x 4)

// ---------------------------------------------------------------------------
// CONVERGED KERNEL — final. 45.05-45.22 us across four independent benches
// (5.95 TB/s effective on a ~96%-write 268 MB stream); every perturbation of
// grid size, MLP, register budget, launch structure, Phase-A amortization,
// and store path measured slower or equal over rounds 1-14.
//
// Block = (2048-pixel range, 16-channel chunk, batch); 512 threads at the
// 4-block/SM cap (2048 thr/SM) -> 2048 blocks = 3.46 waves, required to keep
// the store stream saturated (grid-scaling experiments R7/R8/R11).
//
// Phase A: build 4 KB smem inverse map for this block's 2048-pixel range by
//          scanning batch b's 512 locations (1 per thread, L2-resident).
//          int64-vs-int32 layout detected via __syncthreads_and on odd int32
//          words (all-zero <=> int64; under int32 these are x coords
//          ~U[0,128), P(all 512 zero) ~ 2^-3584).
// Phase B: per q: 4 predicated LDG.128 (one per entity slot), register
//          transpose, 4 streaming STG.128 (warp = 512B contiguous, 128B-
//          aligned bursts -> full-line writes, no write-allocate reads).
//          Only 4 float4s live -> 32 regs, ~82% achieved occupancy.
__global__ void __launch_bounds__(TPB, 4) fused_scatter_kernel(
        const float4* __restrict__ xin,
        const int*    __restrict__ loc32,
        float4*       __restrict__ out) {
    __shared__ short s_inv[PPB];

    const int t  = threadIdx.x;
    const int b  = blockIdx.z;
    const int n0 = blockIdx.y * NCH;
    const int p0 = blockIdx.x * PPB;          // first pixel of this block

    // --- Phase A: smem inverse map ----------------------------------------
    ((int*)s_inv)[2 * t]     = -1;            // 4 shorts = -1 per thread
    ((int*)s_inv)[2 * t + 1] = -1;

    const int* locb32 = loc32 + b * MM * 2;   // int32 view of batch b
    const int* locb64 = loc32 + b * MM * 4;   // int64 view (int32 pairs)

    // layout probe (doubles as the barrier ordering smem init vs scatter):
    int is64 = __syncthreads_and(loc32[2 * t + 1] == 0);

    {
        int e = t;                            // entity m in [0, 512)
        int y, x;
        if (is64) { y = locb64[4 * e]; x = locb64[4 * e + 2]; }
        else      { y = locb32[2 * e]; x = locb32[2 * e + 1]; }
        int rel = y * WPX + x - p0;
        if ((unsigned)rel < PPB) s_inv[rel] = (short)e;
    }
    __syncthreads();

    // --- Phase B: pipelined gather + zero-fill ----------------------------
    short4 iv = ((const short4*)s_inv)[t];
    int m0 = iv.x, m1 = iv.y, m2 = iv.z, m3 = iv.w;
    bool v0 = m0 >= 0, v1 = m1 >= 0, v2 = m2 >= 0, v3 = m3 >= 0;
    int i0 = m0 * (NN / 4), i1 = m1 * (NN / 4);
    int i2 = m2 * (NN / 4), i3 = m3 * (NN / 4);

    // x[b][m][n0 + 0..15] = 4 float4s at row stride NN/4 = 32.
    const float4* xb = xin + b * (MM * NN / 4) + (n0 >> 2);
    float4*       o  = out + (b * NN + n0) * HW4 + (p0 >> 2) + t;
    const float4  z  = make_float4(0.f, 0.f, 0.f, 0.f);

    #pragma unroll
    for (int q = 0; q < 4; q++) {
        float4 a = v0 ? __ldg(xb + i0 + q) : z;
        float4 c = v1 ? __ldg(xb + i1 + q) : z;
        float4 d = v2 ? __ldg(xb + i2 + q) : z;
        float4 f = v3 ? __ldg(xb + i3 + q) : z;

        __stcs(o + (4 * q + 0) * HW4, make_float4(a.x, c.x, d.x, f.x));
        __stcs(o + (4 * q + 1) * HW4, make_float4(a.y, c.y, d.y, f.y));
        __stcs(o + (4 * q + 2) * HW4, make_float4(a.z, c.z, d.z, f.z));
        __stcs(o + (4 * q + 3) * HW4, make_float4(a.w, c.w, d.w, f.w));
    }
}

// ---------------------------------------------------------------------------
extern "C" void kernel_launch(void* const* d_in, const int* in_sizes, int n_in,
                              void* d_out, int out_size) {
    const float* x     = (const float*)d_in[0];
    const int*   loc32 = (const int*)d_in[1];
    float*       out   = (float*)d_out;
    (void)in_sizes; (void)n_in; (void)out_size;

    // One launch: (8 pixel-ranges, 8 channel-chunks, 32 batches) x 512 thr.
    fused_scatter_kernel<<<dim3(HWPX / PPB, NN / NCH, BB), TPB>>>(
        (const float4*)x, loc32, (float4*)out);
}